// round 2
// baseline (speedup 1.0000x reference)
#include <cuda_runtime.h>
#include <math.h>

// Problem constants (fixed shapes for this problem)
#define MAXN 20000
#define MAXE 320000
#define SED  768
#define HC1  512      // 4 heads * 128
#define C1   128
#define H1   4
#define C2   128

// ---------------- scratch (no allocation allowed; bss device globals) ----------------
__device__ __align__(16) float g_h1[MAXN * HC1];     // layer1 pre-attention features
__device__ __align__(16) float g_act1[MAXN * HC1];   // layer1 output after elu
__device__ __align__(16) float g_h3[MAXN * C2];      // layer2 pre-attention features
__device__ __align__(16) float g_esrc1[MAXN * 4];
__device__ __align__(16) float g_edst1[MAXN * 4];
__device__ float g_esrc2[MAXN];
__device__ float g_edst2[MAXN];
__device__ __align__(16) float g_c1[HC1];            // sent @ W1[768:] constant vector
__device__ int g_cnt[MAXN];
__device__ int g_rowptr[MAXN + 1];
__device__ int g_cursor[MAXN];
__device__ int g_col[MAXE];

__device__ __forceinline__ float lrelu(float x) { return x > 0.f ? x : 0.2f * x; }

// ---------------- CSR build ----------------
__global__ void k_zero_cnt(int N) {
    int i = blockIdx.x * blockDim.x + threadIdx.x;
    if (i < N) g_cnt[i] = 0;
}

__global__ void k_count(const int* __restrict__ ei, int E) {
    int i = blockIdx.x * blockDim.x + threadIdx.x;
    if (i < E) atomicAdd(&g_cnt[ei[E + i]], 1);
}

__global__ void k_scan(int N) {
    __shared__ int sm[1024];
    __shared__ int carry;
    int t = threadIdx.x;
    if (t == 0) { carry = 0; g_rowptr[0] = 0; }
    __syncthreads();
    for (int base = 0; base < N; base += 1024) {
        int i = base + t;
        int v = (i < N) ? g_cnt[i] : 0;
        sm[t] = v;
        __syncthreads();
        for (int off = 1; off < 1024; off <<= 1) {
            int u = (t >= off) ? sm[t - off] : 0;
            __syncthreads();
            sm[t] += u;
            __syncthreads();
        }
        int incl = sm[t];
        if (i < N) {
            g_rowptr[i + 1] = carry + incl;
            g_cursor[i] = carry + incl - v;
        }
        __syncthreads();
        if (t == 0) carry += sm[1023];
        __syncthreads();
    }
}

__global__ void k_scatter(const int* __restrict__ ei, int E) {
    int i = blockIdx.x * blockDim.x + threadIdx.x;
    if (i < E) {
        int dst = ei[E + i], src = ei[i];
        int pos = atomicAdd(&g_cursor[dst], 1);
        g_col[pos] = src;
    }
}

// ---------------- constant vector: c1 = sent @ W1[768:1536, :] ----------------
__global__ void k_constvec(const float* __restrict__ sent, const float* __restrict__ W1) {
    int j = blockIdx.x * blockDim.x + threadIdx.x;
    if (j < HC1) {
        float s = 0.f;
        for (int k = 0; k < SED; k++)
            s += sent[k] * W1[(size_t)(SED + k) * HC1 + j];
        g_c1[j] = s;
    }
}

// ---------------- fp32 tiled GEMM: C[M,N] = A[M,K] @ B[K,N] (+ addv[col]) ----------------
// 128x128 block tile, K-tile 8, 256 threads, 8x8 micro-tile (split 4+4 for vector LDS).
// Requires N % 128 == 0, K % 8 == 0, rows bounds-checked.
__global__ void k_gemm(const float* __restrict__ A, const float* __restrict__ B,
                       float* __restrict__ C, const float* __restrict__ addv,
                       int M, int N, int K) {
    __shared__ float As[8][128];
    __shared__ float Bs[8][128];
    int tid = threadIdx.x;
    int tx = tid % 16, ty = tid / 16;
    int m0 = blockIdx.x * 128, n0 = blockIdx.y * 128;
    float acc[8][8];
#pragma unroll
    for (int i = 0; i < 8; i++)
#pragma unroll
        for (int j = 0; j < 8; j++) acc[i][j] = 0.f;

    int ar = tid >> 1;          // 0..127 (A row in tile)
    int ak = (tid & 1) * 4;     // 0 or 4
    int bk = tid >> 5;          // 0..7
    int bn = (tid & 31) * 4;    // 0..124

    for (int k0 = 0; k0 < K; k0 += 8) {
        float4 av = make_float4(0.f, 0.f, 0.f, 0.f);
        int arow = m0 + ar;
        if (arow < M) av = *(const float4*)&A[(size_t)arow * K + k0 + ak];
        As[ak + 0][ar] = av.x; As[ak + 1][ar] = av.y;
        As[ak + 2][ar] = av.z; As[ak + 3][ar] = av.w;
        *(float4*)&Bs[bk][bn] = *(const float4*)&B[(size_t)(k0 + bk) * N + n0 + bn];
        __syncthreads();
#pragma unroll
        for (int kk = 0; kk < 8; kk++) {
            float4 a0 = *(float4*)&As[kk][ty * 4];
            float4 a1 = *(float4*)&As[kk][ty * 4 + 64];
            float4 b0 = *(float4*)&Bs[kk][tx * 4];
            float4 b1 = *(float4*)&Bs[kk][tx * 4 + 64];
            float a[8] = {a0.x, a0.y, a0.z, a0.w, a1.x, a1.y, a1.z, a1.w};
            float b[8] = {b0.x, b0.y, b0.z, b0.w, b1.x, b1.y, b1.z, b1.w};
#pragma unroll
            for (int i = 0; i < 8; i++)
#pragma unroll
                for (int j = 0; j < 8; j++) acc[i][j] = fmaf(a[i], b[j], acc[i][j]);
        }
        __syncthreads();
    }
#pragma unroll
    for (int ig = 0; ig < 2; ig++)
#pragma unroll
        for (int ii = 0; ii < 4; ii++) {
            int r = m0 + ty * 4 + ig * 64 + ii;
            if (r < M) {
#pragma unroll
                for (int jg = 0; jg < 2; jg++) {
                    int cb = n0 + tx * 4 + jg * 64;
                    float4 v;
                    v.x = acc[ig * 4 + ii][jg * 4 + 0];
                    v.y = acc[ig * 4 + ii][jg * 4 + 1];
                    v.z = acc[ig * 4 + ii][jg * 4 + 2];
                    v.w = acc[ig * 4 + ii][jg * 4 + 3];
                    if (addv) {
                        v.x += addv[cb + 0]; v.y += addv[cb + 1];
                        v.z += addv[cb + 2]; v.w += addv[cb + 3];
                    }
                    *(float4*)&C[(size_t)r * N + cb] = v;
                }
            }
        }
}

// ---------------- attention dot products ----------------
__global__ void k_edot1(const float* __restrict__ a_src, const float* __restrict__ a_dst) {
    int n = blockIdx.x;
    int t = threadIdx.x, lane = t & 31, w = t >> 5;  // warp w = head w
    const float* hrow = &g_h1[(size_t)n * HC1 + w * C1];
    float s1 = 0.f, s2 = 0.f;
#pragma unroll
    for (int c = lane; c < C1; c += 32) {
        float v = hrow[c];
        s1 += v * a_src[w * C1 + c];
        s2 += v * a_dst[w * C1 + c];
    }
#pragma unroll
    for (int off = 16; off; off >>= 1) {
        s1 += __shfl_xor_sync(0xffffffffu, s1, off);
        s2 += __shfl_xor_sync(0xffffffffu, s2, off);
    }
    if (lane == 0) { g_esrc1[n * 4 + w] = s1; g_edst1[n * 4 + w] = s2; }
}

__global__ void k_edot2(const float* __restrict__ a_src, const float* __restrict__ a_dst, int N) {
    int t = threadIdx.x, lane = t & 31, w = t >> 5;
    int n = blockIdx.x * 4 + w;
    if (n >= N) return;
    const float* hrow = &g_h3[(size_t)n * C2];
    float s1 = 0.f, s2 = 0.f;
#pragma unroll
    for (int c = lane; c < C2; c += 32) {
        float v = hrow[c];
        s1 += v * a_src[c];
        s2 += v * a_dst[c];
    }
#pragma unroll
    for (int off = 16; off; off >>= 1) {
        s1 += __shfl_xor_sync(0xffffffffu, s1, off);
        s2 += __shfl_xor_sync(0xffffffffu, s2, off);
    }
    if (lane == 0) { g_esrc2[n] = s1; g_edst2[n] = s2; }
}

// ---------------- layer 1 aggregation (4 heads, 128 ch): softmax + gather + elu ----------------
__global__ void k_agg1(const float* __restrict__ b1) {
    int n = blockIdx.x;
    int t = threadIdx.x, lane = t & 31, w = t >> 5;
    int start = g_rowptr[n], end = g_rowptr[n + 1];
    float4 edv = *(const float4*)&g_edst1[n * 4];
    float ed[4] = {edv.x, edv.y, edv.z, edv.w};

    __shared__ float sred[4][4];
    __shared__ float smh[4];
    __shared__ float4 wbuf[128];
    __shared__ int scol[128];

    // ---- phase 1: per-head max ----
    float m[4] = {-3.4e38f, -3.4e38f, -3.4e38f, -3.4e38f};
    for (int i = start + t; i < end; i += 128) {
        int s = g_col[i];
        float4 es = *(const float4*)&g_esrc1[s * 4];
        m[0] = fmaxf(m[0], lrelu(es.x + ed[0]));
        m[1] = fmaxf(m[1], lrelu(es.y + ed[1]));
        m[2] = fmaxf(m[2], lrelu(es.z + ed[2]));
        m[3] = fmaxf(m[3], lrelu(es.w + ed[3]));
    }
#pragma unroll
    for (int h = 0; h < 4; h++)
#pragma unroll
        for (int off = 16; off; off >>= 1)
            m[h] = fmaxf(m[h], __shfl_xor_sync(0xffffffffu, m[h], off));
    if (lane == 0) { sred[0][w] = m[0]; sred[1][w] = m[1]; sred[2][w] = m[2]; sred[3][w] = m[3]; }
    __syncthreads();
    if (t < 4) smh[t] = fmaxf(fmaxf(sred[t][0], sred[t][1]), fmaxf(sred[t][2], sred[t][3]));
    __syncthreads();
    m[0] = smh[0]; m[1] = smh[1]; m[2] = smh[2]; m[3] = smh[3];

    // ---- phase 2: per-head sum of exp ----
    float s4[4] = {0.f, 0.f, 0.f, 0.f};
    for (int i = start + t; i < end; i += 128) {
        int sc = g_col[i];
        float4 es = *(const float4*)&g_esrc1[sc * 4];
        s4[0] += __expf(lrelu(es.x + ed[0]) - m[0]);
        s4[1] += __expf(lrelu(es.y + ed[1]) - m[1]);
        s4[2] += __expf(lrelu(es.z + ed[2]) - m[2]);
        s4[3] += __expf(lrelu(es.w + ed[3]) - m[3]);
    }
#pragma unroll
    for (int h = 0; h < 4; h++)
#pragma unroll
        for (int off = 16; off; off >>= 1)
            s4[h] += __shfl_xor_sync(0xffffffffu, s4[h], off);
    __syncthreads();   // sred reuse: all prior reads done
    if (lane == 0) { sred[0][w] = s4[0]; sred[1][w] = s4[1]; sred[2][w] = s4[2]; sred[3][w] = s4[3]; }
    __syncthreads();
    if (t < 4) smh[t] = 1.f / (sred[t][0] + sred[t][1] + sred[t][2] + sred[t][3] + 1e-16f);
    __syncthreads();
    float inv[4] = {smh[0], smh[1], smh[2], smh[3]};

    // ---- phase 3: weighted gather, chunks of 128 edges ----
    float acc[4] = {0.f, 0.f, 0.f, 0.f};
    for (int base = start; base < end; base += 128) {
        int i = base + t;
        if (i < end) {
            int sc = g_col[i];
            float4 es = *(const float4*)&g_esrc1[sc * 4];
            float4 wv;
            wv.x = __expf(lrelu(es.x + ed[0]) - m[0]) * inv[0];
            wv.y = __expf(lrelu(es.y + ed[1]) - m[1]) * inv[1];
            wv.z = __expf(lrelu(es.z + ed[2]) - m[2]) * inv[2];
            wv.w = __expf(lrelu(es.w + ed[3]) - m[3]) * inv[3];
            wbuf[t] = wv;
            scol[t] = sc;
        }
        __syncthreads();
        int cnt = min(128, end - base);
        for (int j = 0; j < cnt; j++) {
            int sc = scol[j];
            float4 wv = wbuf[j];
            const float* hs = &g_h1[(size_t)sc * HC1];
            acc[0] = fmaf(wv.x, hs[t], acc[0]);
            acc[1] = fmaf(wv.y, hs[128 + t], acc[1]);
            acc[2] = fmaf(wv.z, hs[256 + t], acc[2]);
            acc[3] = fmaf(wv.w, hs[384 + t], acc[3]);
        }
        __syncthreads();
    }
    float* orow = &g_act1[(size_t)n * HC1];
#pragma unroll
    for (int h = 0; h < 4; h++) {
        float v = acc[h] + b1[h * C1 + t];
        orow[h * C1 + t] = v > 0.f ? v : expm1f(v);
    }
}

// ---------------- layer 2 aggregation (1 head, 128 ch) -> final output ----------------
__global__ void k_agg2(const float* __restrict__ b2, float* __restrict__ out) {
    int n = blockIdx.x;
    int t = threadIdx.x, lane = t & 31, w = t >> 5;
    int start = g_rowptr[n], end = g_rowptr[n + 1];
    float ed = g_edst2[n];

    __shared__ float sred[4];
    __shared__ float sh_m, sh_inv;
    __shared__ float wbuf[128];
    __shared__ int scol[128];

    float m = -3.4e38f;
    for (int i = start + t; i < end; i += 128)
        m = fmaxf(m, lrelu(g_esrc2[g_col[i]] + ed));
#pragma unroll
    for (int off = 16; off; off >>= 1) m = fmaxf(m, __shfl_xor_sync(0xffffffffu, m, off));
    if (lane == 0) sred[w] = m;
    __syncthreads();
    if (t == 0) sh_m = fmaxf(fmaxf(sred[0], sred[1]), fmaxf(sred[2], sred[3]));
    __syncthreads();
    m = sh_m;

    float s = 0.f;
    for (int i = start + t; i < end; i += 128)
        s += __expf(lrelu(g_esrc2[g_col[i]] + ed) - m);
#pragma unroll
    for (int off = 16; off; off >>= 1) s += __shfl_xor_sync(0xffffffffu, s, off);
    __syncthreads();
    if (lane == 0) sred[w] = s;
    __syncthreads();
    if (t == 0) sh_inv = 1.f / (sred[0] + sred[1] + sred[2] + sred[3] + 1e-16f);
    __syncthreads();
    float inv = sh_inv;

    float acc = 0.f;
    for (int base = start; base < end; base += 128) {
        int i = base + t;
        if (i < end) {
            int sc = g_col[i];
            wbuf[t] = __expf(lrelu(g_esrc2[sc] + ed) - m) * inv;
            scol[t] = sc;
        }
        __syncthreads();
        int cnt = min(128, end - base);
        for (int j = 0; j < cnt; j++)
            acc = fmaf(wbuf[j], g_h3[(size_t)scol[j] * C2 + t], acc);
        __syncthreads();
    }
    out[(size_t)n * C2 + t] = acc + b2[t];
}

// ---------------- launch ----------------
extern "C" void kernel_launch(void* const* d_in, const int* in_sizes, int n_in,
                              void* d_out, int out_size) {
    const float* x    = (const float*)d_in[0];
    const int*   ei   = (const int*)d_in[1];
    const float* sent = (const float*)d_in[2];
    const float* W1   = (const float*)d_in[3];
    const float* a1s  = (const float*)d_in[4];
    const float* a1d  = (const float*)d_in[5];
    const float* b1   = (const float*)d_in[6];
    const float* W2   = (const float*)d_in[7];
    const float* a2s  = (const float*)d_in[8];
    const float* a2d  = (const float*)d_in[9];
    const float* b2   = (const float*)d_in[10];
    float* out = (float*)d_out;

    int N = in_sizes[0] / SED;   // 20000
    int E = in_sizes[1] / 2;     // 320000

    float *p_h1, *p_act1, *p_h3, *p_c1;
    cudaGetSymbolAddress((void**)&p_h1,   g_h1);
    cudaGetSymbolAddress((void**)&p_act1, g_act1);
    cudaGetSymbolAddress((void**)&p_h3,   g_h3);
    cudaGetSymbolAddress((void**)&p_c1,   g_c1);

    // CSR build (dst-sorted)
    k_zero_cnt<<<(N + 255) / 256, 256>>>(N);
    k_count<<<(E + 255) / 256, 256>>>(ei, E);
    k_scan<<<1, 1024>>>(N);
    k_scatter<<<(E + 255) / 256, 256>>>(ei, E);

    // Layer 1
    k_constvec<<<2, 256>>>(sent, W1);
    k_gemm<<<dim3((N + 127) / 128, HC1 / 128), 256>>>(x, W1, p_h1, p_c1, N, HC1, SED);
    k_edot1<<<N, 128>>>(a1s, a1d);
    k_agg1<<<N, 128>>>(b1);

    // Layer 2
    k_gemm<<<dim3((N + 127) / 128, C2 / 128), 256>>>(p_act1, W2, p_h3, nullptr, N, C2, HC1);
    k_edot2<<<(N + 3) / 4, 128>>>(a2s, a2d, N);
    k_agg2<<<N, 128>>>(b2, out);
}

// round 3
// speedup vs baseline: 1.8018x; 1.8018x over previous
#include <cuda_runtime.h>
#include <math.h>

// Problem constants (fixed shapes for this problem)
#define MAXN 20000
#define MAXE 320000
#define SED  768
#define HC1  512      // 4 heads * 128
#define C1   128
#define H1   4
#define C2   128

// ---------------- scratch (no allocation allowed; bss device globals) ----------------
__device__ __align__(16) float g_h1[MAXN * HC1];     // layer1 pre-attention features
__device__ __align__(16) float g_act1[MAXN * HC1];   // layer1 output after elu
__device__ __align__(16) float g_h3[MAXN * C2];      // layer2 pre-attention features
__device__ __align__(16) float g_esrc1[MAXN * 4];
__device__ __align__(16) float g_edst1[MAXN * 4];
__device__ float g_esrc2[MAXN];
__device__ float g_edst2[MAXN];
__device__ __align__(16) float g_c1[HC1];            // sent @ W1[768:] constant vector
__device__ int g_cnt[MAXN];
__device__ int g_rowptr[MAXN + 1];
__device__ int g_cursor[MAXN];
__device__ int g_col[MAXE];

__device__ __forceinline__ float lrelu(float x) { return x > 0.f ? x : 0.2f * x; }

__device__ __forceinline__ unsigned f2tf32(float f) {
    unsigned o;
    asm("cvt.rna.tf32.f32 %0, %1;" : "=r"(o) : "f"(f));
    return o;
}

// ---------------- CSR build ----------------
__global__ void k_zero_cnt(int N) {
    int i = blockIdx.x * blockDim.x + threadIdx.x;
    if (i < N) g_cnt[i] = 0;
}

__global__ void k_count(const int* __restrict__ ei, int E) {
    int i = blockIdx.x * blockDim.x + threadIdx.x;
    if (i < E) atomicAdd(&g_cnt[ei[E + i]], 1);
}

__global__ void k_scan(int N) {
    __shared__ int sm[1024];
    __shared__ int carry;
    int t = threadIdx.x;
    if (t == 0) { carry = 0; g_rowptr[0] = 0; }
    __syncthreads();
    for (int base = 0; base < N; base += 1024) {
        int i = base + t;
        int v = (i < N) ? g_cnt[i] : 0;
        sm[t] = v;
        __syncthreads();
        for (int off = 1; off < 1024; off <<= 1) {
            int u = (t >= off) ? sm[t - off] : 0;
            __syncthreads();
            sm[t] += u;
            __syncthreads();
        }
        int incl = sm[t];
        if (i < N) {
            g_rowptr[i + 1] = carry + incl;
            g_cursor[i] = carry + incl - v;
        }
        __syncthreads();
        if (t == 0) carry += sm[1023];
        __syncthreads();
    }
}

__global__ void k_scatter(const int* __restrict__ ei, int E) {
    int i = blockIdx.x * blockDim.x + threadIdx.x;
    if (i < E) {
        int dst = ei[E + i], src = ei[i];
        int pos = atomicAdd(&g_cursor[dst], 1);
        g_col[pos] = src;
    }
}

// ---------------- constant vector: c1 = sent @ W1[768:1536, :] ----------------
__global__ void k_constvec(const float* __restrict__ sent, const float* __restrict__ W1) {
    int j = blockIdx.x * blockDim.x + threadIdx.x;
    if (j < HC1) {
        float s = 0.f;
        for (int k = 0; k < SED; k++)
            s += sent[k] * W1[(size_t)(SED + k) * HC1 + j];
        g_c1[j] = s;
    }
}

// ---------------- TF32 tensor-core GEMM: C[M,N] = A[M,K] @ B[K,N] (+ addv[col]) ----------------
// Block tile 128x128, K-tile 16, 256 threads (8 warps as 2x4, each warp 64x32).
// mma.sync.aligned.m16n8k8.row.col.f32.tf32.tf32.f32 with a k-permutation so that
// thread t consumes physical k slots {2t, 2t+1}: A fragments become float2 LDS,
// B fragments are two scalar LDS from adjacent k rows. Double-buffered smem.
// Requires N % 128 == 0, K % 16 == 0; M bounds-checked.
#define LDA 24
#define LDB 132
__global__ __launch_bounds__(256, 2)
void k_gemm_tf32(const float* __restrict__ A, const float* __restrict__ B,
                 float* __restrict__ C, const float* __restrict__ addv,
                 int M, int N, int K) {
    __shared__ float As[2][128 * LDA];
    __shared__ float Bs[2][16 * LDB];

    int tid = threadIdx.x;
    int lane = tid & 31, wid = tid >> 5;
    int g = lane >> 2, t = lane & 3;
    int wm = (wid >> 2) * 64, wn = (wid & 3) * 32;
    int m0 = blockIdx.x * 128, n0 = blockIdx.y * 128;

    // global load assignment
    int a_row = tid >> 1;            // 0..127
    int a_k   = (tid & 1) * 4;       // 0 or 4 (second f4 at +8)
    int b_kr  = tid >> 5;            // 0..7 (second row at +8)
    int b_n   = (tid & 31) * 4;      // 0..124

    bool a_ok = (m0 + a_row) < M;
    const float* Aptr = A + (size_t)(m0 + a_row) * K;
    const float* Bptr = B + (size_t)n0;

    float acc[4][4][4];
#pragma unroll
    for (int mi = 0; mi < 4; mi++)
#pragma unroll
        for (int ni = 0; ni < 4; ni++)
#pragma unroll
            for (int c = 0; c < 4; c++) acc[mi][ni][c] = 0.f;

    float4 ra0, ra1, rb0, rb1;
    const float4 fz = make_float4(0.f, 0.f, 0.f, 0.f);

    // prologue: tile 0
    {
        int kb = 0;
        ra0 = a_ok ? *(const float4*)&Aptr[kb + a_k]     : fz;
        ra1 = a_ok ? *(const float4*)&Aptr[kb + a_k + 8] : fz;
        rb0 = *(const float4*)&Bptr[(size_t)(kb + b_kr) * N + b_n];
        rb1 = *(const float4*)&Bptr[(size_t)(kb + b_kr + 8) * N + b_n];
        float* as = &As[0][a_row * LDA + a_k];
        as[0] = __uint_as_float(f2tf32(ra0.x)); as[1] = __uint_as_float(f2tf32(ra0.y));
        as[2] = __uint_as_float(f2tf32(ra0.z)); as[3] = __uint_as_float(f2tf32(ra0.w));
        as[8] = __uint_as_float(f2tf32(ra1.x)); as[9] = __uint_as_float(f2tf32(ra1.y));
        as[10] = __uint_as_float(f2tf32(ra1.z)); as[11] = __uint_as_float(f2tf32(ra1.w));
        float* bs0 = &Bs[0][b_kr * LDB + b_n];
        float* bs1 = &Bs[0][(b_kr + 8) * LDB + b_n];
        bs0[0] = __uint_as_float(f2tf32(rb0.x)); bs0[1] = __uint_as_float(f2tf32(rb0.y));
        bs0[2] = __uint_as_float(f2tf32(rb0.z)); bs0[3] = __uint_as_float(f2tf32(rb0.w));
        bs1[0] = __uint_as_float(f2tf32(rb1.x)); bs1[1] = __uint_as_float(f2tf32(rb1.y));
        bs1[2] = __uint_as_float(f2tf32(rb1.z)); bs1[3] = __uint_as_float(f2tf32(rb1.w));
    }
    __syncthreads();

    int nk = K / 16;
    for (int kt = 0; kt < nk; kt++) {
        int cur = kt & 1;
        if (kt + 1 < nk) {
            int kb = (kt + 1) * 16;
            ra0 = a_ok ? *(const float4*)&Aptr[kb + a_k]     : fz;
            ra1 = a_ok ? *(const float4*)&Aptr[kb + a_k + 8] : fz;
            rb0 = *(const float4*)&Bptr[(size_t)(kb + b_kr) * N + b_n];
            rb1 = *(const float4*)&Bptr[(size_t)(kb + b_kr + 8) * N + b_n];
        }

        // compute on buffer cur: 2 k-steps of 8
        const float* as = As[cur];
        const float* bs = Bs[cur];
#pragma unroll
        for (int ks = 0; ks < 2; ks++) {
            int kb = ks * 8;
            float2 af[4][2];
#pragma unroll
            for (int mi = 0; mi < 4; mi++) {
                int r = wm + mi * 16 + g;
                af[mi][0] = *(const float2*)&as[r * LDA + kb + 2 * t];
                af[mi][1] = *(const float2*)&as[(r + 8) * LDA + kb + 2 * t];
            }
#pragma unroll
            for (int ni = 0; ni < 4; ni++) {
                int cidx = wn + ni * 8 + g;
                unsigned b0 = __float_as_uint(bs[(kb + 2 * t) * LDB + cidx]);
                unsigned b1 = __float_as_uint(bs[(kb + 2 * t + 1) * LDB + cidx]);
#pragma unroll
                for (int mi = 0; mi < 4; mi++) {
                    unsigned a0 = __float_as_uint(af[mi][0].x);   // row g,   k 2t
                    unsigned a1 = __float_as_uint(af[mi][1].x);   // row g+8, k 2t
                    unsigned a2 = __float_as_uint(af[mi][0].y);   // row g,   k 2t+1
                    unsigned a3 = __float_as_uint(af[mi][1].y);   // row g+8, k 2t+1
                    asm volatile(
                        "mma.sync.aligned.m16n8k8.row.col.f32.tf32.tf32.f32 "
                        "{%0,%1,%2,%3}, {%4,%5,%6,%7}, {%8,%9}, {%0,%1,%2,%3};"
                        : "+f"(acc[mi][ni][0]), "+f"(acc[mi][ni][1]),
                          "+f"(acc[mi][ni][2]), "+f"(acc[mi][ni][3])
                        : "r"(a0), "r"(a1), "r"(a2), "r"(a3), "r"(b0), "r"(b1));
                }
            }
        }

        if (kt + 1 < nk) {
            int nxt = (kt + 1) & 1;
            float* asw = &As[nxt][a_row * LDA + a_k];
            asw[0] = __uint_as_float(f2tf32(ra0.x)); asw[1] = __uint_as_float(f2tf32(ra0.y));
            asw[2] = __uint_as_float(f2tf32(ra0.z)); asw[3] = __uint_as_float(f2tf32(ra0.w));
            asw[8] = __uint_as_float(f2tf32(ra1.x)); asw[9] = __uint_as_float(f2tf32(ra1.y));
            asw[10] = __uint_as_float(f2tf32(ra1.z)); asw[11] = __uint_as_float(f2tf32(ra1.w));
            float* bs0 = &Bs[nxt][b_kr * LDB + b_n];
            float* bs1 = &Bs[nxt][(b_kr + 8) * LDB + b_n];
            bs0[0] = __uint_as_float(f2tf32(rb0.x)); bs0[1] = __uint_as_float(f2tf32(rb0.y));
            bs0[2] = __uint_as_float(f2tf32(rb0.z)); bs0[3] = __uint_as_float(f2tf32(rb0.w));
            bs1[0] = __uint_as_float(f2tf32(rb1.x)); bs1[1] = __uint_as_float(f2tf32(rb1.y));
            bs1[2] = __uint_as_float(f2tf32(rb1.z)); bs1[3] = __uint_as_float(f2tf32(rb1.w));
            __syncthreads();
        }
    }

    // epilogue: C fragment layout: c0,c1 -> row g cols 2t,2t+1; c2,c3 -> row g+8
#pragma unroll
    for (int mi = 0; mi < 4; mi++) {
#pragma unroll
        for (int half = 0; half < 2; half++) {
            int r = m0 + wm + mi * 16 + g + half * 8;
            if (r < M) {
#pragma unroll
                for (int ni = 0; ni < 4; ni++) {
                    int c = n0 + wn + ni * 8 + 2 * t;
                    float2 v;
                    v.x = acc[mi][ni][half * 2 + 0];
                    v.y = acc[mi][ni][half * 2 + 1];
                    if (addv) { v.x += addv[c]; v.y += addv[c + 1]; }
                    *(float2*)&C[(size_t)r * N + c] = v;
                }
            }
        }
    }
}

// ---------------- attention dot products ----------------
__global__ void k_edot1(const float* __restrict__ a_src, const float* __restrict__ a_dst) {
    int n = blockIdx.x;
    int t = threadIdx.x, lane = t & 31, w = t >> 5;  // warp w = head w
    const float* hrow = &g_h1[(size_t)n * HC1 + w * C1];
    float s1 = 0.f, s2 = 0.f;
#pragma unroll
    for (int c = lane; c < C1; c += 32) {
        float v = hrow[c];
        s1 += v * a_src[w * C1 + c];
        s2 += v * a_dst[w * C1 + c];
    }
#pragma unroll
    for (int off = 16; off; off >>= 1) {
        s1 += __shfl_xor_sync(0xffffffffu, s1, off);
        s2 += __shfl_xor_sync(0xffffffffu, s2, off);
    }
    if (lane == 0) { g_esrc1[n * 4 + w] = s1; g_edst1[n * 4 + w] = s2; }
}

__global__ void k_edot2(const float* __restrict__ a_src, const float* __restrict__ a_dst, int N) {
    int t = threadIdx.x, lane = t & 31, w = t >> 5;
    int n = blockIdx.x * 4 + w;
    if (n >= N) return;
    const float* hrow = &g_h3[(size_t)n * C2];
    float s1 = 0.f, s2 = 0.f;
#pragma unroll
    for (int c = lane; c < C2; c += 32) {
        float v = hrow[c];
        s1 += v * a_src[c];
        s2 += v * a_dst[c];
    }
#pragma unroll
    for (int off = 16; off; off >>= 1) {
        s1 += __shfl_xor_sync(0xffffffffu, s1, off);
        s2 += __shfl_xor_sync(0xffffffffu, s2, off);
    }
    if (lane == 0) { g_esrc2[n] = s1; g_edst2[n] = s2; }
}

// ---------------- layer 1 aggregation (4 heads, 128 ch): softmax + gather + elu ----------------
__global__ void k_agg1(const float* __restrict__ b1) {
    int n = blockIdx.x;
    int t = threadIdx.x, lane = t & 31, w = t >> 5;
    int start = g_rowptr[n], end = g_rowptr[n + 1];
    float4 edv = *(const float4*)&g_edst1[n * 4];
    float ed[4] = {edv.x, edv.y, edv.z, edv.w};

    __shared__ float sred[4][4];
    __shared__ float smh[4];
    __shared__ float4 wbuf[128];
    __shared__ int scol[128];

    // ---- phase 1: per-head max ----
    float m[4] = {-3.4e38f, -3.4e38f, -3.4e38f, -3.4e38f};
    for (int i = start + t; i < end; i += 128) {
        int s = g_col[i];
        float4 es = *(const float4*)&g_esrc1[s * 4];
        m[0] = fmaxf(m[0], lrelu(es.x + ed[0]));
        m[1] = fmaxf(m[1], lrelu(es.y + ed[1]));
        m[2] = fmaxf(m[2], lrelu(es.z + ed[2]));
        m[3] = fmaxf(m[3], lrelu(es.w + ed[3]));
    }
#pragma unroll
    for (int h = 0; h < 4; h++)
#pragma unroll
        for (int off = 16; off; off >>= 1)
            m[h] = fmaxf(m[h], __shfl_xor_sync(0xffffffffu, m[h], off));
    if (lane == 0) { sred[0][w] = m[0]; sred[1][w] = m[1]; sred[2][w] = m[2]; sred[3][w] = m[3]; }
    __syncthreads();
    if (t < 4) smh[t] = fmaxf(fmaxf(sred[t][0], sred[t][1]), fmaxf(sred[t][2], sred[t][3]));
    __syncthreads();
    m[0] = smh[0]; m[1] = smh[1]; m[2] = smh[2]; m[3] = smh[3];

    // ---- phase 2: per-head sum of exp ----
    float s4[4] = {0.f, 0.f, 0.f, 0.f};
    for (int i = start + t; i < end; i += 128) {
        int sc = g_col[i];
        float4 es = *(const float4*)&g_esrc1[sc * 4];
        s4[0] += __expf(lrelu(es.x + ed[0]) - m[0]);
        s4[1] += __expf(lrelu(es.y + ed[1]) - m[1]);
        s4[2] += __expf(lrelu(es.z + ed[2]) - m[2]);
        s4[3] += __expf(lrelu(es.w + ed[3]) - m[3]);
    }
#pragma unroll
    for (int h = 0; h < 4; h++)
#pragma unroll
        for (int off = 16; off; off >>= 1)
            s4[h] += __shfl_xor_sync(0xffffffffu, s4[h], off);
    __syncthreads();   // sred reuse: all prior reads done
    if (lane == 0) { sred[0][w] = s4[0]; sred[1][w] = s4[1]; sred[2][w] = s4[2]; sred[3][w] = s4[3]; }
    __syncthreads();
    if (t < 4) smh[t] = 1.f / (sred[t][0] + sred[t][1] + sred[t][2] + sred[t][3] + 1e-16f);
    __syncthreads();
    float inv[4] = {smh[0], smh[1], smh[2], smh[3]};

    // ---- phase 3: weighted gather, chunks of 128 edges ----
    float acc[4] = {0.f, 0.f, 0.f, 0.f};
    for (int base = start; base < end; base += 128) {
        int i = base + t;
        if (i < end) {
            int sc = g_col[i];
            float4 es = *(const float4*)&g_esrc1[sc * 4];
            float4 wv;
            wv.x = __expf(lrelu(es.x + ed[0]) - m[0]) * inv[0];
            wv.y = __expf(lrelu(es.y + ed[1]) - m[1]) * inv[1];
            wv.z = __expf(lrelu(es.z + ed[2]) - m[2]) * inv[2];
            wv.w = __expf(lrelu(es.w + ed[3]) - m[3]) * inv[3];
            wbuf[t] = wv;
            scol[t] = sc;
        }
        __syncthreads();
        int cnt = min(128, end - base);
        for (int j = 0; j < cnt; j++) {
            int sc = scol[j];
            float4 wv = wbuf[j];
            const float* hs = &g_h1[(size_t)sc * HC1];
            acc[0] = fmaf(wv.x, hs[t], acc[0]);
            acc[1] = fmaf(wv.y, hs[128 + t], acc[1]);
            acc[2] = fmaf(wv.z, hs[256 + t], acc[2]);
            acc[3] = fmaf(wv.w, hs[384 + t], acc[3]);
        }
        __syncthreads();
    }
    float* orow = &g_act1[(size_t)n * HC1];
#pragma unroll
    for (int h = 0; h < 4; h++) {
        float v = acc[h] + b1[h * C1 + t];
        orow[h * C1 + t] = v > 0.f ? v : expm1f(v);
    }
}

// ---------------- layer 2 aggregation (1 head, 128 ch) -> final output ----------------
__global__ void k_agg2(const float* __restrict__ b2, float* __restrict__ out) {
    int n = blockIdx.x;
    int t = threadIdx.x, lane = t & 31, w = t >> 5;
    int start = g_rowptr[n], end = g_rowptr[n + 1];
    float ed = g_edst2[n];

    __shared__ float sred[4];
    __shared__ float sh_m, sh_inv;
    __shared__ float wbuf[128];
    __shared__ int scol[128];

    float m = -3.4e38f;
    for (int i = start + t; i < end; i += 128)
        m = fmaxf(m, lrelu(g_esrc2[g_col[i]] + ed));
#pragma unroll
    for (int off = 16; off; off >>= 1) m = fmaxf(m, __shfl_xor_sync(0xffffffffu, m, off));
    if (lane == 0) sred[w] = m;
    __syncthreads();
    if (t == 0) sh_m = fmaxf(fmaxf(sred[0], sred[1]), fmaxf(sred[2], sred[3]));
    __syncthreads();
    m = sh_m;

    float s = 0.f;
    for (int i = start + t; i < end; i += 128)
        s += __expf(lrelu(g_esrc2[g_col[i]] + ed) - m);
#pragma unroll
    for (int off = 16; off; off >>= 1) s += __shfl_xor_sync(0xffffffffu, s, off);
    __syncthreads();
    if (lane == 0) sred[w] = s;
    __syncthreads();
    if (t == 0) sh_inv = 1.f / (sred[0] + sred[1] + sred[2] + sred[3] + 1e-16f);
    __syncthreads();
    float inv = sh_inv;

    float acc = 0.f;
    for (int base = start; base < end; base += 128) {
        int i = base + t;
        if (i < end) {
            int sc = g_col[i];
            wbuf[t] = __expf(lrelu(g_esrc2[sc] + ed) - m) * inv;
            scol[t] = sc;
        }
        __syncthreads();
        int cnt = min(128, end - base);
        for (int j = 0; j < cnt; j++)
            acc = fmaf(wbuf[j], g_h3[(size_t)scol[j] * C2 + t], acc);
        __syncthreads();
    }
    out[(size_t)n * C2 + t] = acc + b2[t];
}

// ---------------- launch ----------------
extern "C" void kernel_launch(void* const* d_in, const int* in_sizes, int n_in,
                              void* d_out, int out_size) {
    const float* x    = (const float*)d_in[0];
    const int*   ei   = (const int*)d_in[1];
    const float* sent = (const float*)d_in[2];
    const float* W1   = (const float*)d_in[3];
    const float* a1s  = (const float*)d_in[4];
    const float* a1d  = (const float*)d_in[5];
    const float* b1   = (const float*)d_in[6];
    const float* W2   = (const float*)d_in[7];
    const float* a2s  = (const float*)d_in[8];
    const float* a2d  = (const float*)d_in[9];
    const float* b2   = (const float*)d_in[10];
    float* out = (float*)d_out;

    int N = in_sizes[0] / SED;   // 20000
    int E = in_sizes[1] / 2;     // 320000

    float *p_h1, *p_act1, *p_h3, *p_c1;
    cudaGetSymbolAddress((void**)&p_h1,   g_h1);
    cudaGetSymbolAddress((void**)&p_act1, g_act1);
    cudaGetSymbolAddress((void**)&p_h3,   g_h3);
    cudaGetSymbolAddress((void**)&p_c1,   g_c1);

    // CSR build (dst-sorted)
    k_zero_cnt<<<(N + 255) / 256, 256>>>(N);
    k_count<<<(E + 255) / 256, 256>>>(ei, E);
    k_scan<<<1, 1024>>>(N);
    k_scatter<<<(E + 255) / 256, 256>>>(ei, E);

    // Layer 1
    k_constvec<<<2, 256>>>(sent, W1);
    k_gemm_tf32<<<dim3((N + 127) / 128, HC1 / 128), 256>>>(x, W1, p_h1, p_c1, N, HC1, SED);
    k_edot1<<<N, 128>>>(a1s, a1d);
    k_agg1<<<N, 128>>>(b1);

    // Layer 2
    k_gemm_tf32<<<dim3((N + 127) / 128, C2 / 128), 256>>>(p_act1, W2, p_h3, nullptr, N, C2, HC1);
    k_edot2<<<(N + 3) / 4, 128>>>(a2s, a2d, N);
    k_agg2<<<N, 128>>>(b2, out);
}

// round 4
// speedup vs baseline: 2.0244x; 1.1236x over previous
#include <cuda_runtime.h>
#include <math.h>

// Problem constants (fixed shapes for this problem)
#define MAXN 20000
#define MAXE 320000
#define SED  768
#define HC1  512      // 4 heads * 128
#define C1   128
#define H1   4
#define C2   128

// ---------------- scratch (no allocation allowed; bss device globals) ----------------
__device__ __align__(16) float g_h1[MAXN * HC1];     // layer1 pre-attention features
__device__ __align__(16) float g_act1[MAXN * HC1];   // layer1 output after elu
__device__ __align__(16) float g_h3[MAXN * C2];      // layer2 pre-attention features
__device__ __align__(16) float g_esrc1[MAXN * 4];
__device__ __align__(16) float g_edst1[MAXN * 4];
__device__ float g_esrc2[MAXN];
__device__ float g_edst2[MAXN];
__device__ __align__(16) float g_c1[HC1];            // sent @ W1[768:] constant vector
__device__ int g_cnt[MAXN];
__device__ int g_rowptr[MAXN + 1];
__device__ int g_cursor[MAXN];
__device__ int g_col[MAXE];
__device__ int g_bsum[64];
__device__ int g_boff[64];

__device__ __forceinline__ float lrelu(float x) { return x > 0.f ? x : 0.2f * x; }

__device__ __forceinline__ unsigned f2tf32(float f) {
    unsigned o;
    asm("cvt.rna.tf32.f32 %0, %1;" : "=r"(o) : "f"(f));
    return o;
}

// ---------------- CSR build ----------------
__global__ void k_count(const int* __restrict__ ei, int E) {
    int i = blockIdx.x * blockDim.x + threadIdx.x;
    if (i < E) atomicAdd(&g_cnt[ei[E + i]], 1);
}

// local inclusive scan of 512-element tiles; block totals to g_bsum
__global__ void k_scan1(int N) {
    __shared__ int sm[512];
    int b = blockIdx.x, t = threadIdx.x, i = b * 512 + t;
    int v = (i < N) ? g_cnt[i] : 0;
    sm[t] = v;
    __syncthreads();
#pragma unroll
    for (int off = 1; off < 512; off <<= 1) {
        int u = (t >= off) ? sm[t - off] : 0;
        __syncthreads();
        sm[t] += u;
        __syncthreads();
    }
    if (i < N) g_rowptr[i + 1] = sm[t];   // local inclusive, offset added later
    if (t == 511) g_bsum[b] = sm[511];
}

// exclusive scan of block totals (nb <= 64), one block of 64 threads
__global__ void k_scan2(int nb) {
    __shared__ int sm[64];
    int t = threadIdx.x;
    int v = (t < nb) ? g_bsum[t] : 0;
    sm[t] = v;
    __syncthreads();
#pragma unroll
    for (int off = 1; off < 64; off <<= 1) {
        int u = (t >= off) ? sm[t - off] : 0;
        __syncthreads();
        sm[t] += u;
        __syncthreads();
    }
    if (t < nb) g_boff[t] = sm[t] - v;    // exclusive
}

// add block offsets, finalize rowptr + cursor
__global__ void k_scan3(int N) {
    int i = blockIdx.x * blockDim.x + threadIdx.x;
    if (i < N) {
        int r = g_rowptr[i + 1] + g_boff[i >> 9];
        g_rowptr[i + 1] = r;
        g_cursor[i] = r - g_cnt[i];
    }
    if (i == 0) g_rowptr[0] = 0;
}

__global__ void k_scatter(const int* __restrict__ ei, int E) {
    int i = blockIdx.x * blockDim.x + threadIdx.x;
    if (i < E) {
        int dst = ei[E + i], src = ei[i];
        int pos = atomicAdd(&g_cursor[dst], 1);
        g_col[pos] = src;
    }
}

// ---------------- constant vector: c1 = sent @ W1[768:1536, :] ----------------
__global__ void k_constvec(const float* __restrict__ sent, const float* __restrict__ W1) {
    int j = blockIdx.x * blockDim.x + threadIdx.x;
    if (j < HC1) {
        float s = 0.f;
        for (int k = 0; k < SED; k++)
            s += sent[k] * W1[(size_t)(SED + k) * HC1 + j];
        g_c1[j] = s;
    }
}

// ---------------- TF32 tensor-core GEMM: C[M,N] = A[M,K] @ B[K,N] (+ addv[col]) ----------------
#define LDA 24
#define LDB 132
__global__ __launch_bounds__(256, 2)
void k_gemm_tf32(const float* __restrict__ A, const float* __restrict__ B,
                 float* __restrict__ C, const float* __restrict__ addv,
                 int M, int N, int K) {
    __shared__ float As[2][128 * LDA];
    __shared__ float Bs[2][16 * LDB];

    int tid = threadIdx.x;
    int lane = tid & 31, wid = tid >> 5;
    int g = lane >> 2, t = lane & 3;
    int wm = (wid >> 2) * 64, wn = (wid & 3) * 32;
    int m0 = blockIdx.x * 128, n0 = blockIdx.y * 128;

    int a_row = tid >> 1;
    int a_k   = (tid & 1) * 4;
    int b_kr  = tid >> 5;
    int b_n   = (tid & 31) * 4;

    bool a_ok = (m0 + a_row) < M;
    const float* Aptr = A + (size_t)(m0 + a_row) * K;
    const float* Bptr = B + (size_t)n0;

    float acc[4][4][4];
#pragma unroll
    for (int mi = 0; mi < 4; mi++)
#pragma unroll
        for (int ni = 0; ni < 4; ni++)
#pragma unroll
            for (int c = 0; c < 4; c++) acc[mi][ni][c] = 0.f;

    float4 ra0, ra1, rb0, rb1;
    const float4 fz = make_float4(0.f, 0.f, 0.f, 0.f);

    {
        int kb = 0;
        ra0 = a_ok ? *(const float4*)&Aptr[kb + a_k]     : fz;
        ra1 = a_ok ? *(const float4*)&Aptr[kb + a_k + 8] : fz;
        rb0 = *(const float4*)&Bptr[(size_t)(kb + b_kr) * N + b_n];
        rb1 = *(const float4*)&Bptr[(size_t)(kb + b_kr + 8) * N + b_n];
        float* as = &As[0][a_row * LDA + a_k];
        as[0] = __uint_as_float(f2tf32(ra0.x)); as[1] = __uint_as_float(f2tf32(ra0.y));
        as[2] = __uint_as_float(f2tf32(ra0.z)); as[3] = __uint_as_float(f2tf32(ra0.w));
        as[8] = __uint_as_float(f2tf32(ra1.x)); as[9] = __uint_as_float(f2tf32(ra1.y));
        as[10] = __uint_as_float(f2tf32(ra1.z)); as[11] = __uint_as_float(f2tf32(ra1.w));
        float* bs0 = &Bs[0][b_kr * LDB + b_n];
        float* bs1 = &Bs[0][(b_kr + 8) * LDB + b_n];
        bs0[0] = __uint_as_float(f2tf32(rb0.x)); bs0[1] = __uint_as_float(f2tf32(rb0.y));
        bs0[2] = __uint_as_float(f2tf32(rb0.z)); bs0[3] = __uint_as_float(f2tf32(rb0.w));
        bs1[0] = __uint_as_float(f2tf32(rb1.x)); bs1[1] = __uint_as_float(f2tf32(rb1.y));
        bs1[2] = __uint_as_float(f2tf32(rb1.z)); bs1[3] = __uint_as_float(f2tf32(rb1.w));
    }
    __syncthreads();

    int nk = K / 16;
    for (int kt = 0; kt < nk; kt++) {
        int cur = kt & 1;
        if (kt + 1 < nk) {
            int kb = (kt + 1) * 16;
            ra0 = a_ok ? *(const float4*)&Aptr[kb + a_k]     : fz;
            ra1 = a_ok ? *(const float4*)&Aptr[kb + a_k + 8] : fz;
            rb0 = *(const float4*)&Bptr[(size_t)(kb + b_kr) * N + b_n];
            rb1 = *(const float4*)&Bptr[(size_t)(kb + b_kr + 8) * N + b_n];
        }

        const float* as = As[cur];
        const float* bs = Bs[cur];
#pragma unroll
        for (int ks = 0; ks < 2; ks++) {
            int kb = ks * 8;
            float2 af[4][2];
#pragma unroll
            for (int mi = 0; mi < 4; mi++) {
                int r = wm + mi * 16 + g;
                af[mi][0] = *(const float2*)&as[r * LDA + kb + 2 * t];
                af[mi][1] = *(const float2*)&as[(r + 8) * LDA + kb + 2 * t];
            }
#pragma unroll
            for (int ni = 0; ni < 4; ni++) {
                int cidx = wn + ni * 8 + g;
                unsigned b0 = __float_as_uint(bs[(kb + 2 * t) * LDB + cidx]);
                unsigned b1 = __float_as_uint(bs[(kb + 2 * t + 1) * LDB + cidx]);
#pragma unroll
                for (int mi = 0; mi < 4; mi++) {
                    unsigned a0 = __float_as_uint(af[mi][0].x);
                    unsigned a1 = __float_as_uint(af[mi][1].x);
                    unsigned a2 = __float_as_uint(af[mi][0].y);
                    unsigned a3 = __float_as_uint(af[mi][1].y);
                    asm volatile(
                        "mma.sync.aligned.m16n8k8.row.col.f32.tf32.tf32.f32 "
                        "{%0,%1,%2,%3}, {%4,%5,%6,%7}, {%8,%9}, {%0,%1,%2,%3};"
                        : "+f"(acc[mi][ni][0]), "+f"(acc[mi][ni][1]),
                          "+f"(acc[mi][ni][2]), "+f"(acc[mi][ni][3])
                        : "r"(a0), "r"(a1), "r"(a2), "r"(a3), "r"(b0), "r"(b1));
                }
            }
        }

        if (kt + 1 < nk) {
            int nxt = (kt + 1) & 1;
            float* asw = &As[nxt][a_row * LDA + a_k];
            asw[0] = __uint_as_float(f2tf32(ra0.x)); asw[1] = __uint_as_float(f2tf32(ra0.y));
            asw[2] = __uint_as_float(f2tf32(ra0.z)); asw[3] = __uint_as_float(f2tf32(ra0.w));
            asw[8] = __uint_as_float(f2tf32(ra1.x)); asw[9] = __uint_as_float(f2tf32(ra1.y));
            asw[10] = __uint_as_float(f2tf32(ra1.z)); asw[11] = __uint_as_float(f2tf32(ra1.w));
            float* bs0 = &Bs[nxt][b_kr * LDB + b_n];
            float* bs1 = &Bs[nxt][(b_kr + 8) * LDB + b_n];
            bs0[0] = __uint_as_float(f2tf32(rb0.x)); bs0[1] = __uint_as_float(f2tf32(rb0.y));
            bs0[2] = __uint_as_float(f2tf32(rb0.z)); bs0[3] = __uint_as_float(f2tf32(rb0.w));
            bs1[0] = __uint_as_float(f2tf32(rb1.x)); bs1[1] = __uint_as_float(f2tf32(rb1.y));
            bs1[2] = __uint_as_float(f2tf32(rb1.z)); bs1[3] = __uint_as_float(f2tf32(rb1.w));
            __syncthreads();
        }
    }

#pragma unroll
    for (int mi = 0; mi < 4; mi++) {
#pragma unroll
        for (int half = 0; half < 2; half++) {
            int r = m0 + wm + mi * 16 + g + half * 8;
            if (r < M) {
#pragma unroll
                for (int ni = 0; ni < 4; ni++) {
                    int c = n0 + wn + ni * 8 + 2 * t;
                    float2 v;
                    v.x = acc[mi][ni][half * 2 + 0];
                    v.y = acc[mi][ni][half * 2 + 1];
                    if (addv) { v.x += addv[c]; v.y += addv[c + 1]; }
                    *(float2*)&C[(size_t)r * N + c] = v;
                }
            }
        }
    }
}

// ---------------- attention dot products ----------------
__global__ void k_edot1(const float* __restrict__ a_src, const float* __restrict__ a_dst) {
    int n = blockIdx.x;
    int t = threadIdx.x, lane = t & 31, w = t >> 5;
    const float* hrow = &g_h1[(size_t)n * HC1 + w * C1];
    float s1 = 0.f, s2 = 0.f;
#pragma unroll
    for (int c = lane; c < C1; c += 32) {
        float v = hrow[c];
        s1 += v * a_src[w * C1 + c];
        s2 += v * a_dst[w * C1 + c];
    }
#pragma unroll
    for (int off = 16; off; off >>= 1) {
        s1 += __shfl_xor_sync(0xffffffffu, s1, off);
        s2 += __shfl_xor_sync(0xffffffffu, s2, off);
    }
    if (lane == 0) { g_esrc1[n * 4 + w] = s1; g_edst1[n * 4 + w] = s2; }
}

__global__ void k_edot2(const float* __restrict__ a_src, const float* __restrict__ a_dst, int N) {
    int t = threadIdx.x, lane = t & 31, w = t >> 5;
    int n = blockIdx.x * 4 + w;
    if (n >= N) return;
    const float* hrow = &g_h3[(size_t)n * C2];
    float s1 = 0.f, s2 = 0.f;
#pragma unroll
    for (int c = lane; c < C2; c += 32) {
        float v = hrow[c];
        s1 += v * a_src[c];
        s2 += v * a_dst[c];
    }
#pragma unroll
    for (int off = 16; off; off >>= 1) {
        s1 += __shfl_xor_sync(0xffffffffu, s1, off);
        s2 += __shfl_xor_sync(0xffffffffu, s2, off);
    }
    if (lane == 0) { g_esrc2[n] = s1; g_edst2[n] = s2; }
}

// ---------------- layer 1 aggregation: single-sweep softmax-free normalization ----------------
// alpha_j = exp(e_j)/sum(exp(e)) == softmax with max-shift (ratio-invariant; e bounded ~|8|).
// One edge sweep: accumulate unnormalized sum + denominator, normalize at end.
__global__ void k_agg1(const float* __restrict__ b1) {
    int n = blockIdx.x;
    int t = threadIdx.x, lane = t & 31, w = t >> 5;
    int start = g_rowptr[n], end = g_rowptr[n + 1];
    float4 edv = *(const float4*)&g_edst1[n * 4];

    __shared__ float4 wbuf[128];
    __shared__ int scol[128];
    __shared__ float sred[4][4];

    float acc[4] = {0.f, 0.f, 0.f, 0.f};
    float ss[4]  = {0.f, 0.f, 0.f, 0.f};

    for (int base = start; base < end; base += 128) {
        int i = base + t;
        if (i < end) {
            int sc = g_col[i];
            float4 es = *(const float4*)&g_esrc1[sc * 4];
            float4 wv;
            wv.x = __expf(lrelu(es.x + edv.x));
            wv.y = __expf(lrelu(es.y + edv.y));
            wv.z = __expf(lrelu(es.z + edv.z));
            wv.w = __expf(lrelu(es.w + edv.w));
            ss[0] += wv.x; ss[1] += wv.y; ss[2] += wv.z; ss[3] += wv.w;
            wbuf[t] = wv;
            scol[t] = sc;
        }
        __syncthreads();
        int cnt = min(128, end - base);
        int j = 0;
        for (; j + 1 < cnt; j += 2) {
            int s0 = scol[j], s1 = scol[j + 1];
            float4 w0 = wbuf[j], w1 = wbuf[j + 1];
            const float* p0 = &g_h1[(size_t)s0 * HC1];
            const float* p1 = &g_h1[(size_t)s1 * HC1];
            float v00 = p0[t], v01 = p0[128 + t], v02 = p0[256 + t], v03 = p0[384 + t];
            float v10 = p1[t], v11 = p1[128 + t], v12 = p1[256 + t], v13 = p1[384 + t];
            acc[0] = fmaf(w0.x, v00, acc[0]);
            acc[1] = fmaf(w0.y, v01, acc[1]);
            acc[2] = fmaf(w0.z, v02, acc[2]);
            acc[3] = fmaf(w0.w, v03, acc[3]);
            acc[0] = fmaf(w1.x, v10, acc[0]);
            acc[1] = fmaf(w1.y, v11, acc[1]);
            acc[2] = fmaf(w1.z, v12, acc[2]);
            acc[3] = fmaf(w1.w, v13, acc[3]);
        }
        if (j < cnt) {
            int s0 = scol[j];
            float4 w0 = wbuf[j];
            const float* p0 = &g_h1[(size_t)s0 * HC1];
            acc[0] = fmaf(w0.x, p0[t],       acc[0]);
            acc[1] = fmaf(w0.y, p0[128 + t], acc[1]);
            acc[2] = fmaf(w0.z, p0[256 + t], acc[2]);
            acc[3] = fmaf(w0.w, p0[384 + t], acc[3]);
        }
        __syncthreads();
    }

    // block-reduce denominators (once)
#pragma unroll
    for (int h = 0; h < 4; h++)
#pragma unroll
        for (int off = 16; off; off >>= 1)
            ss[h] += __shfl_xor_sync(0xffffffffu, ss[h], off);
    if (lane == 0) { sred[0][w] = ss[0]; sred[1][w] = ss[1]; sred[2][w] = ss[2]; sred[3][w] = ss[3]; }
    __syncthreads();

    float* orow = &g_act1[(size_t)n * HC1];
#pragma unroll
    for (int h = 0; h < 4; h++) {
        float s = sred[h][0] + sred[h][1] + sred[h][2] + sred[h][3];
        float inv = (s > 0.f) ? 1.f / s : 0.f;   // deg-0 node -> out = bias
        float v = acc[h] * inv + b1[h * C1 + t];
        orow[h * C1 + t] = v > 0.f ? v : expm1f(v);
    }
}

// ---------------- layer 2 aggregation (1 head) -> final output ----------------
__global__ void k_agg2(const float* __restrict__ b2, float* __restrict__ out) {
    int n = blockIdx.x;
    int t = threadIdx.x, lane = t & 31, w = t >> 5;
    int start = g_rowptr[n], end = g_rowptr[n + 1];
    float ed = g_edst2[n];

    __shared__ float wbuf[128];
    __shared__ int scol[128];
    __shared__ float sred[4];

    float acc = 0.f, ss = 0.f;

    for (int base = start; base < end; base += 128) {
        int i = base + t;
        if (i < end) {
            int sc = g_col[i];
            float wv = __expf(lrelu(g_esrc2[sc] + ed));
            ss += wv;
            wbuf[t] = wv;
            scol[t] = sc;
        }
        __syncthreads();
        int cnt = min(128, end - base);
        int j = 0;
        for (; j + 3 < cnt; j += 4) {
            int s0 = scol[j], s1 = scol[j + 1], s2 = scol[j + 2], s3 = scol[j + 3];
            float w0 = wbuf[j], w1 = wbuf[j + 1], w2 = wbuf[j + 2], w3 = wbuf[j + 3];
            float v0 = g_h3[(size_t)s0 * C2 + t];
            float v1 = g_h3[(size_t)s1 * C2 + t];
            float v2 = g_h3[(size_t)s2 * C2 + t];
            float v3 = g_h3[(size_t)s3 * C2 + t];
            acc = fmaf(w0, v0, acc);
            acc = fmaf(w1, v1, acc);
            acc = fmaf(w2, v2, acc);
            acc = fmaf(w3, v3, acc);
        }
        for (; j < cnt; j++)
            acc = fmaf(wbuf[j], g_h3[(size_t)scol[j] * C2 + t], acc);
        __syncthreads();
    }

#pragma unroll
    for (int off = 16; off; off >>= 1) ss += __shfl_xor_sync(0xffffffffu, ss, off);
    if (lane == 0) sred[w] = ss;
    __syncthreads();
    float s = sred[0] + sred[1] + sred[2] + sred[3];
    float inv = (s > 0.f) ? 1.f / s : 0.f;
    out[(size_t)n * C2 + t] = acc * inv + b2[t];
}

// ---------------- launch ----------------
extern "C" void kernel_launch(void* const* d_in, const int* in_sizes, int n_in,
                              void* d_out, int out_size) {
    const float* x    = (const float*)d_in[0];
    const int*   ei   = (const int*)d_in[1];
    const float* sent = (const float*)d_in[2];
    const float* W1   = (const float*)d_in[3];
    const float* a1s  = (const float*)d_in[4];
    const float* a1d  = (const float*)d_in[5];
    const float* b1   = (const float*)d_in[6];
    const float* W2   = (const float*)d_in[7];
    const float* a2s  = (const float*)d_in[8];
    const float* a2d  = (const float*)d_in[9];
    const float* b2   = (const float*)d_in[10];
    float* out = (float*)d_out;

    int N = in_sizes[0] / SED;   // 20000
    int E = in_sizes[1] / 2;     // 320000
    int nb = (N + 511) / 512;    // scan blocks (<=64)

    float *p_h1, *p_act1, *p_h3, *p_c1;
    int *p_cnt;
    cudaGetSymbolAddress((void**)&p_h1,   g_h1);
    cudaGetSymbolAddress((void**)&p_act1, g_act1);
    cudaGetSymbolAddress((void**)&p_h3,   g_h3);
    cudaGetSymbolAddress((void**)&p_c1,   g_c1);
    cudaGetSymbolAddress((void**)&p_cnt,  g_cnt);

    // CSR build (dst-sorted)
    cudaMemsetAsync(p_cnt, 0, N * sizeof(int));
    k_count<<<(E + 255) / 256, 256>>>(ei, E);
    k_scan1<<<nb, 512>>>(N);
    k_scan2<<<1, 64>>>(nb);
    k_scan3<<<(N + 255) / 256, 256>>>(N);
    k_scatter<<<(E + 255) / 256, 256>>>(ei, E);

    // Layer 1
    k_constvec<<<2, 256>>>(sent, W1);
    k_gemm_tf32<<<dim3((N + 127) / 128, HC1 / 128), 256>>>(x, W1, p_h1, p_c1, N, HC1, SED);
    k_edot1<<<N, 128>>>(a1s, a1d);
    k_agg1<<<N, 128>>>(b1);

    // Layer 2
    k_gemm_tf32<<<dim3((N + 127) / 128, C2 / 128), 256>>>(p_act1, W2, p_h3, nullptr, N, C2, HC1);
    k_edot2<<<(N + 3) / 4, 128>>>(a2s, a2d, N);
    k_agg2<<<N, 128>>>(b2, out);
}